// round 6
// baseline (speedup 1.0000x reference)
#include <cuda_runtime.h>
#include <math.h>

typedef unsigned long long ull;

#define NDIM 512
#define DDIM 784
#define CDIM 10
#define ITERS 40
#define QMAX 127.0f

#define MT 8          // row tiles (64 rows each)
#define NT 16         // column groups (8 cols each)
#define GRID (MT*NT)  // 128 CTAs
#define TPB 512

// shared layout (float offsets)
#define ZSTR 20               // duplicated-z row stride (16 used + 4 pad)
#define S_Z   0               // 2 x 512*20 = 20480
#define S_RED 20480           // 16 splits * 528 ([col][row], col stride 66)
#define S_UX  28928           // 512
#define SMEM_FLOATS 29440
#define SMEM_BYTES (SMEM_FLOATS*4)

// ---- device globals (scratch) ----
__device__ float g_Ux[NDIM*128];
__device__ float g_zA[NDIM*128];
__device__ float g_zB[NDIM*128];
__device__ unsigned g_maxW, g_maxU, g_maxB;
__device__ unsigned g_gcnt, g_ggen;              // full-grid barrier
__device__ unsigned g_cnt[NT*8], g_gen[NT*8];    // per-group barriers (32B spaced)

// -------- release/acquire barrier --------
__device__ __forceinline__ void gbar(unsigned* cnt, unsigned* gen, unsigned expected) {
    __syncthreads();
    if (threadIdx.x == 0) {
        unsigned snap, t;
        asm volatile("ld.acquire.gpu.global.u32 %0, [%1];" : "=r"(snap) : "l"(gen) : "memory");
        asm volatile("atom.acq_rel.gpu.global.add.u32 %0, [%1], %2;"
                     : "=r"(t) : "l"(cnt), "r"(1u) : "memory");
        if (t == expected - 1u) {
            asm volatile("st.relaxed.gpu.global.u32 [%0], %1;" :: "l"(cnt), "r"(0u) : "memory");
            asm volatile("red.release.gpu.global.add.u32 [%0], %1;" :: "l"(gen), "r"(1u) : "memory");
        } else {
            unsigned g;
            do {
                asm volatile("ld.acquire.gpu.global.u32 %0, [%1];" : "=r"(g) : "l"(gen) : "memory");
            } while (g == snap);
        }
    }
    __syncthreads();
}

// -------- f32x2 helpers --------
__device__ __forceinline__ ull pk2(float x){
    ull d; asm("mov.b64 %0, {%1,%1};" : "=l"(d) : "r"(__float_as_uint(x))); return d;
}
__device__ __forceinline__ ull pk2b(float x, float y){
    ull d; asm("mov.b64 %0, {%1,%2};" : "=l"(d) : "r"(__float_as_uint(x)), "r"(__float_as_uint(y))); return d;
}
__device__ __forceinline__ void upk2(ull v, float& x, float& y){
    unsigned a, b; asm("mov.b64 {%0,%1}, %2;" : "=r"(a), "=r"(b) : "l"(v));
    x = __uint_as_float(a); y = __uint_as_float(b);
}
__device__ __forceinline__ void fma2(ull& d, ull a, ull b){
    asm("fma.rn.f32x2 %0, %1, %2, %3;" : "=l"(d) : "l"(a), "l"(b), "l"(d));
}
__device__ __forceinline__ float warpmax(float v){
    #pragma unroll
    for (int o = 16; o; o >>= 1) v = fmaxf(v, __shfl_xor_sync(0xffffffffu, v, o));
    return v;
}

extern "C" __global__ void __launch_bounds__(TPB, 1)
mondeq_kernel(const float* __restrict__ W, const float* __restrict__ U,
              const float* __restrict__ bvec, const float* __restrict__ x,
              const float* __restrict__ Wc, const float* __restrict__ bcv,
              float* __restrict__ out)
{
    extern __shared__ float sm[];
    float* sZ   = sm + S_Z;
    float* sRed = sm + S_RED;
    float* sUx  = sm + S_UX;

    const int tid  = threadIdx.x;
    const int cta  = blockIdx.x;
    const int mi   = cta & (MT - 1);   // row tile 0..7
    const int nj   = cta >> 3;         // column group 0..15
    const int wid  = tid >> 5;         // warp = k-split 0..15 (32 k each)
    const int lane = tid & 31;         // row-pair within tile (rows 2*lane, 2*lane+1)
    unsigned* bcnt = &g_cnt[nj*8];
    unsigned* bgen = &g_gen[nj*8];

    // ================= Phase A: per-tensor max|.| =================
    {
        float lw = 0.f, lu = 0.f, lb = 0.f;
        const int gid = cta * TPB + tid;
        for (int i = gid; i < NDIM*NDIM; i += GRID*TPB) lw = fmaxf(lw, fabsf(W[i]));
        for (int i = gid; i < NDIM*DDIM; i += GRID*TPB) lu = fmaxf(lu, fabsf(U[i]));
        if (gid < NDIM) lb = fabsf(bvec[gid]);
        lw = warpmax(lw); lu = warpmax(lu); lb = warpmax(lb);
        if (lane == 0) { sm[wid] = lw; sm[16 + wid] = lu; sm[32 + wid] = lb; }
        __syncthreads();
        if (tid == 0) {
            float mw = 0.f, mu = 0.f, mb = 0.f;
            #pragma unroll
            for (int i = 0; i < 16; ++i) {
                mw = fmaxf(mw, sm[i]); mu = fmaxf(mu, sm[16+i]); mb = fmaxf(mb, sm[32+i]);
            }
            atomicMax(&g_maxW, __float_as_uint(mw));
            atomicMax(&g_maxU, __float_as_uint(mu));
            atomicMax(&g_maxB, __float_as_uint(mb));
        }
    }
    gbar(&g_gcnt, &g_ggen, GRID);

    const float scW = __uint_as_float(__ldcg(&g_maxW)) / QMAX;
    const float scU = __uint_as_float(__ldcg(&g_maxU)) / QMAX;
    const float scB = __uint_as_float(__ldcg(&g_maxB)) / QMAX;

    // ================= Phase B: Ux = Uq @ x^T + bq  (one dot per thread) ==========
    {
        float* xs = sm;            // [112][130] k-major padded
        float* us = sm + 14560;    // 4 x 112
        const int n0   = cta * 4;
        const int rr   = tid >> 7;      // U row 0..3
        const int bcol = tid & 127;     // batch col
        float acc = 0.f;
        for (int ch = 0; ch < 7; ++ch) {
            const int k0 = ch * 112;
            __syncthreads();
            for (int i = tid; i < 128*112; i += TPB) {
                const int bb = i / 112, kk = i - bb*112;
                xs[kk*130 + bb] = x[bb*DDIM + k0 + kk];
            }
            if (tid < 448) {
                const int r2 = tid / 112, kk = tid - r2*112;
                us[r2*112 + kk] = rintf(U[(n0+r2)*DDIM + k0 + kk] / scU) * scU;
            }
            __syncthreads();
            const float* up = us + rr*112;
            #pragma unroll 4
            for (int kk = 0; kk < 112; ++kk)
                acc = fmaf(up[kk], xs[kk*130 + bcol], acc);
        }
        const float bq = rintf(bvec[n0 + rr] / scB) * scB;
        __stcg(&g_Ux[(bcol>>3)*4096 + (n0+rr)*8 + (bcol&7)], acc + bq);
    }

    // ================= Phase C: quantized W -> per-thread registers ================
    // thread holds wreg[k2] = (Wq[mi*64+2*lane][wid*32+k2], Wq[...+2*lane+1][...])
    ull wreg[32];
    #pragma unroll
    for (int k2 = 0; k2 < 32; ++k2) wreg[k2] = 0ull;
    {
        float* tmp = sm;           // [64][261] staged quantized half-tile
        for (int ch = 0; ch < 2; ++ch) {
            __syncthreads();
            for (int i = tid; i < 64*256; i += TPB) {
                const int row = i >> 8, k = i & 255;
                tmp[row*261 + k] =
                    rintf(W[(size_t)(mi*64 + row)*NDIM + ch*256 + k] / scW) * scW;
            }
            __syncthreads();
            if ((wid >> 3) == ch) {
                const int kb = (wid & 7) * 32;
                const float* r0 = tmp + (2*lane)*261 + kb;
                const float* r1 = r0 + 261;
                #pragma unroll
                for (int k2 = 0; k2 < 32; ++k2)
                    wreg[k2] = pk2b(r0[k2], r1[k2]);
            }
        }
    }
    gbar(&g_gcnt, &g_ggen, GRID);   // g_Ux complete everywhere
    if (cta == 0 && tid == 0) { g_maxW = 0u; g_maxU = 0u; g_maxB = 0u; } // replay reset

    // ================= z1 = relu(0.5*Ux): sUx + publish + own dup stage ===========
    const int gout = nj*4096 + mi*512;
    {
        const float v = __ldcg(&g_Ux[gout + tid]);
        sUx[tid] = v;
        const float z1 = fmaxf(0.5f * v, 0.f);
        __stcg(&g_zA[gout + tid], z1);
        const int kk = mi*64 + (tid >> 3), c = tid & 7;
        *(ull*)(sZ + kk*ZSTR + 2*c) = pk2(z1);
    }
    float* gz_cur = g_zA;
    float* gz_nxt = g_zB;
    int cur = 0;

    // combine-phase mapping (tid < 256)
    const int row = tid >> 2;
    const int cp  = (tid & 3) << 1;

    // ================= Main loop: 39 iterations (z2..z40) ==========================
    for (int it = 2; it <= ITERS; ++it) {
        gbar(bcnt, bgen, MT);            // z_{it-1} of all tiles visible

        float* szc = sZ + cur*(512*ZSTR);
        // ---- stage other 7 tiles, duplicated ----
        {
            const int k = tid;           // global z index 0..511
            if ((k >> 6) != mi) {
                const float4 a = __ldcg((const float4*)(gz_cur + nj*4096 + k*8));
                const float4 b = __ldcg((const float4*)(gz_cur + nj*4096 + k*8 + 4));
                ull* d = (ull*)(szc + k*ZSTR);
                d[0] = pk2(a.x); d[1] = pk2(a.y); d[2] = pk2(a.z); d[3] = pk2(a.w);
                d[4] = pk2(b.x); d[5] = pk2(b.y); d[6] = pk2(b.z); d[7] = pk2(b.w);
            }
        }
        __syncthreads();

        // ---- GEMM: W from registers, z broadcast from SMEM ----
        ull acc[8];
        #pragma unroll
        for (int c = 0; c < 8; ++c) acc[c] = 0ull;
        {
            const float* zp = szc + (wid*32)*ZSTR;
            #pragma unroll
            for (int k2 = 0; k2 < 32; ++k2) {
                const float* q = zp + k2*ZSTR;
                const ulonglong2 z01 = *(const ulonglong2*)(q);
                const ulonglong2 z23 = *(const ulonglong2*)(q + 4);
                const ulonglong2 z45 = *(const ulonglong2*)(q + 8);
                const ulonglong2 z67 = *(const ulonglong2*)(q + 12);
                const ull wv = wreg[k2];
                fma2(acc[0], wv, z01.x); fma2(acc[1], wv, z01.y);
                fma2(acc[2], wv, z23.x); fma2(acc[3], wv, z23.y);
                fma2(acc[4], wv, z45.x); fma2(acc[5], wv, z45.y);
                fma2(acc[6], wv, z67.x); fma2(acc[7], wv, z67.y);
            }
        }
        // ---- partials: sRed[split][col][row-pair], col stride 66 ----
        {
            float* rp = sRed + wid*528 + 2*lane;
            #pragma unroll
            for (int c = 0; c < 8; ++c)
                *(ull*)(rp + c*66) = acc[c];
        }
        __syncthreads();

        // ---- combine + relu + publish (tid < 256) ----
        if (tid < 256) {
            float s0 = 0.f, s1 = 0.f;
            const float* rq = sRed + row;
            #pragma unroll
            for (int q = 0; q < 16; ++q) {
                s0 += rq[q*528 + cp*66];
                s1 += rq[q*528 + (cp+1)*66];
            }
            float u0, u1;
            upk2(*(const ull*)(sUx + row*8 + cp), u0, u1);
            const float4 zo = *(const float4*)(szc + (mi*64 + row)*ZSTR + 2*cp);
            const float v0 = fmaf(0.5f, zo.x, 0.5f * (s0 + u0));
            const float v1 = fmaf(0.5f, zo.z, 0.5f * (s1 + u1));
            const float zn0 = fmaxf(v0, 0.f), zn1 = fmaxf(v1, 0.f);
            __stcg((ull*)(gz_nxt + nj*4096 + (mi*64 + row)*8 + cp), pk2b(zn0, zn1));
            float* nb = sZ + (cur^1)*(512*ZSTR) + (mi*64 + row)*ZSTR + 2*cp;
            *(ull*)nb       = pk2(zn0);
            *(ull*)(nb + 2) = pk2(zn1);
        }
        { float* t = gz_cur; gz_cur = gz_nxt; gz_nxt = t; }
        cur ^= 1;
    }

    gbar(bcnt, bgen, MT);   // z40 of all tiles published

    // ================= Classifier (row-tile 0 CTA of each group) ====================
    if (mi == 0 && tid < 8*CDIM) {
        const int bl = tid / CDIM, c = tid - bl*CDIM;
        const float* zp = gz_cur + nj*4096 + bl;
        const float* wc = Wc + c*NDIM;
        float acc = bcv[c];
        #pragma unroll 8
        for (int n = 0; n < NDIM; ++n)
            acc = fmaf(__ldcg(zp + n*8), wc[n], acc);
        out[(nj*8 + bl)*CDIM + c] = acc;
    }
}

extern "C" void kernel_launch(void* const* d_in, const int* in_sizes, int n_in,
                              void* d_out, int out_size) {
    (void)in_sizes; (void)n_in; (void)out_size;
    cudaFuncSetAttribute(mondeq_kernel, cudaFuncAttributeMaxDynamicSharedMemorySize, SMEM_BYTES);
    mondeq_kernel<<<GRID, TPB, SMEM_BYTES>>>(
        (const float*)d_in[0],   // W  (512,512)
        (const float*)d_in[1],   // U  (512,784)
        (const float*)d_in[2],   // b  (512)
        (const float*)d_in[3],   // x  (128,784)
        (const float*)d_in[4],   // Wc (10,512)
        (const float*)d_in[5],   // bc (10)
        (float*)d_out);          // logits (128,10)
}

// round 7
// speedup vs baseline: 1.2039x; 1.2039x over previous
#include <cuda_runtime.h>
#include <math.h>

typedef unsigned long long ull;

#define NDIM 512
#define DDIM 784
#define CDIM 10
#define ITERS 40
#define QMAX 127.0f

#define MT 8          // row tiles (64 rows each)
#define NT 16         // column groups (8 cols each)
#define GRID (MT*NT)  // 128 CTAs
#define TPB 512
#define ZSTR 12       // padded z row stride (8 used + 4 pad), 48B: bank-clean, 16B-aligned

// shared layout (float offsets)
#define S_Z   0               // 2 buffers x 512*12 = 12288
#define S_RED 12288           // 16 warps x 64 rows x stride 12 = 12288
#define S_UX  24576           // 512
#define SMEM_FLOATS 25088
#define SMEM_BYTES (SMEM_FLOATS*4)

// ---- device globals (scratch) ----
__device__ float g_Ux[NDIM*128];
__device__ float g_zA[NDIM*128];
__device__ float g_zB[NDIM*128];
__device__ unsigned g_maxW, g_maxU, g_maxB;
__device__ unsigned g_gcnt, g_ggen;              // full-grid barrier
__device__ unsigned g_cnt[NT*8], g_gen[NT*8];    // per-group barriers (32B spaced)

// -------- full release/acquire barrier (prologue only) --------
__device__ __forceinline__ void gbar(unsigned* cnt, unsigned* gen, unsigned expected) {
    __syncthreads();
    if (threadIdx.x == 0) {
        unsigned snap, t;
        asm volatile("ld.acquire.gpu.global.u32 %0, [%1];" : "=r"(snap) : "l"(gen) : "memory");
        asm volatile("atom.acq_rel.gpu.global.add.u32 %0, [%1], %2;"
                     : "=r"(t) : "l"(cnt), "r"(1u) : "memory");
        if (t == expected - 1u) {
            asm volatile("st.relaxed.gpu.global.u32 [%0], %1;" :: "l"(cnt), "r"(0u) : "memory");
            asm volatile("red.release.gpu.global.add.u32 [%0], %1;" :: "l"(gen), "r"(1u) : "memory");
        } else {
            unsigned g;
            do {
                asm volatile("ld.acquire.gpu.global.u32 %0, [%1];" : "=r"(g) : "l"(gen) : "memory");
            } while (g == snap);
        }
    }
    __syncthreads();
}

// -------- main-loop barrier primitives (generation-target based) --------
__device__ __forceinline__ void bar_arrive(unsigned* cnt, unsigned* gen) {
    unsigned t;
    asm volatile("atom.acq_rel.gpu.global.add.u32 %0, [%1], %2;"
                 : "=r"(t) : "l"(cnt), "r"(1u) : "memory");
    if (t == MT - 1u) {
        asm volatile("st.relaxed.gpu.global.u32 [%0], %1;" :: "l"(cnt), "r"(0u) : "memory");
        asm volatile("red.release.gpu.global.add.u32 [%0], %1;" :: "l"(gen), "r"(1u) : "memory");
    }
}
__device__ __forceinline__ void bar_wait(unsigned* gen, unsigned target) {
    unsigned g;
    do {
        asm volatile("ld.acquire.gpu.global.u32 %0, [%1];" : "=r"(g) : "l"(gen) : "memory");
    } while ((int)(g - target) < 0);
}

// -------- f32x2 helpers --------
__device__ __forceinline__ ull pk2(float x){
    ull d; asm("mov.b64 %0, {%1,%1};" : "=l"(d) : "r"(__float_as_uint(x))); return d;
}
__device__ __forceinline__ void fma2(ull& d, ull a, ull b){
    asm("fma.rn.f32x2 %0, %1, %2, %3;" : "=l"(d) : "l"(a), "l"(b), "l"(d));
}
__device__ __forceinline__ float warpmax(float v){
    #pragma unroll
    for (int o = 16; o; o >>= 1) v = fmaxf(v, __shfl_xor_sync(0xffffffffu, v, o));
    return v;
}

extern "C" __global__ void __launch_bounds__(TPB, 1)
mondeq_kernel(const float* __restrict__ W, const float* __restrict__ U,
              const float* __restrict__ bvec, const float* __restrict__ x,
              const float* __restrict__ Wc, const float* __restrict__ bcv,
              float* __restrict__ out)
{
    extern __shared__ float sm[];
    float* sZ   = sm + S_Z;
    float* sRed = sm + S_RED;
    float* sUx  = sm + S_UX;

    const int tid  = threadIdx.x;
    const int cta  = blockIdx.x;
    const int mi   = cta & (MT - 1);   // row tile 0..7
    const int nj   = cta >> 3;         // column group 0..15
    const int wid  = tid >> 5;         // warp: within-tile k offset = wid*4 (interleaved)
    const int lane = tid & 31;         // rows 2*lane, 2*lane+1 of own tile
    unsigned* bcnt = &g_cnt[nj*8];
    unsigned* bgen = &g_gen[nj*8];

    // ================= Phase A: per-tensor max|.| =================
    {
        float lw = 0.f, lu = 0.f, lb = 0.f;
        const int gid = cta * TPB + tid;
        for (int i = gid; i < NDIM*NDIM; i += GRID*TPB) lw = fmaxf(lw, fabsf(W[i]));
        for (int i = gid; i < NDIM*DDIM; i += GRID*TPB) lu = fmaxf(lu, fabsf(U[i]));
        if (gid < NDIM) lb = fabsf(bvec[gid]);
        lw = warpmax(lw); lu = warpmax(lu); lb = warpmax(lb);
        if (lane == 0) { sm[wid] = lw; sm[16 + wid] = lu; sm[32 + wid] = lb; }
        __syncthreads();
        if (tid == 0) {
            float mw = 0.f, mu = 0.f, mb = 0.f;
            #pragma unroll
            for (int i = 0; i < 16; ++i) {
                mw = fmaxf(mw, sm[i]); mu = fmaxf(mu, sm[16+i]); mb = fmaxf(mb, sm[32+i]);
            }
            atomicMax(&g_maxW, __float_as_uint(mw));
            atomicMax(&g_maxU, __float_as_uint(mu));
            atomicMax(&g_maxB, __float_as_uint(mb));
        }
    }
    gbar(&g_gcnt, &g_ggen, GRID);

    const float scW = __uint_as_float(__ldcg(&g_maxW)) / QMAX;
    const float scU = __uint_as_float(__ldcg(&g_maxU)) / QMAX;
    const float scB = __uint_as_float(__ldcg(&g_maxB)) / QMAX;

    // ================= Phase B: Ux = Uq @ x^T + bq  (one dot per thread) ==========
    {
        float* xs = sm;            // [112][130] k-major padded
        float* us = sm + 14560;    // 4 x 112
        const int n0   = cta * 4;
        const int rr   = tid >> 7;      // U row 0..3
        const int bcol = tid & 127;     // batch col
        float acc = 0.f;
        for (int ch = 0; ch < 7; ++ch) {
            const int k0 = ch * 112;
            __syncthreads();
            for (int i = tid; i < 128*112; i += TPB) {
                const int bb = i / 112, kk = i - bb*112;
                xs[kk*130 + bb] = x[bb*DDIM + k0 + kk];
            }
            if (tid < 448) {
                const int r2 = tid / 112, kk = tid - r2*112;
                us[r2*112 + kk] = rintf(U[(n0+r2)*DDIM + k0 + kk] / scU) * scU;
            }
            __syncthreads();
            const float* up = us + rr*112;
            #pragma unroll 4
            for (int kk = 0; kk < 112; ++kk)
                acc = fmaf(up[kk], xs[kk*130 + bcol], acc);
        }
        const float bq = rintf(bvec[n0 + rr] / scB) * scB;
        __stcg(&g_Ux[(bcol>>3)*4096 + (n0+rr)*8 + (bcol&7)], acc + bq);
        __syncthreads();
    }

    // ================= Phase C: quantized W -> per-thread scalar registers =========
    // thread (wid, lane) holds rows {2*lane, 2*lane+1}, k = t*64 + wid*4 + j2
    float w0[32], w1[32];
    {
        const float* Wr0 = W + (size_t)(mi*64 + 2*lane)*NDIM;
        const float* Wr1 = Wr0 + NDIM;
        #pragma unroll
        for (int t = 0; t < 8; ++t) {
            const int k0 = t*64 + wid*4;
            const float4 a = *(const float4*)(Wr0 + k0);
            const float4 b = *(const float4*)(Wr1 + k0);
            w0[t*4+0] = rintf(a.x/scW)*scW; w0[t*4+1] = rintf(a.y/scW)*scW;
            w0[t*4+2] = rintf(a.z/scW)*scW; w0[t*4+3] = rintf(a.w/scW)*scW;
            w1[t*4+0] = rintf(b.x/scW)*scW; w1[t*4+1] = rintf(b.y/scW)*scW;
            w1[t*4+2] = rintf(b.z/scW)*scW; w1[t*4+3] = rintf(b.w/scW)*scW;
        }
    }
    gbar(&g_gcnt, &g_ggen, GRID);   // g_Ux complete everywhere
    if (cta == 0 && tid == 0) { g_maxW = 0u; g_maxU = 0u; g_maxB = 0u; } // replay reset

    // ================= z1 = relu(0.5*Ux): sUx + publish + local stage ==============
    unsigned gen0 = 0u;
    if (tid == 0)
        asm volatile("ld.relaxed.gpu.global.u32 %0, [%1];" : "=r"(gen0) : "l"(bgen) : "memory");
    {
        const float v = __ldcg(&g_Ux[nj*4096 + mi*512 + tid]);
        sUx[tid] = v;
        const float z1 = fmaxf(0.5f * v, 0.f);
        __stcg(&g_zA[nj*4096 + mi*512 + tid], z1);
        sZ[(mi*64 + (tid>>3))*ZSTR + (tid&7)] = z1;   // buffer 0, own region
    }
    __syncthreads();
    if (tid == 0) bar_arrive(bcnt, bgen);             // z1 published
    float* gz_cur = g_zA;
    float* gz_nxt = g_zB;
    int cur = 0;

    const int r = tid >> 3;          // combine row 0..63
    const int c = tid & 7;           // combine col 0..7

    // ================= Main loop: 39 iterations (z2..z40) ==========================
    for (int it = 2; it <= ITERS; ++it) {
        if (tid == 0) bar_wait(bgen, gen0 + (unsigned)(it - 1));
        __syncthreads();

        float* szc = sZ + cur*6144;
        // ---- stage other 7 tiles (own tile staged locally last iter) ----
        if ((tid >> 6) != mi) {
            const float4 a = __ldcg((const float4*)(gz_cur + nj*4096 + tid*8));
            const float4 b = __ldcg((const float4*)(gz_cur + nj*4096 + tid*8 + 4));
            *(float4*)(szc + tid*ZSTR)     = a;
            *(float4*)(szc + tid*ZSTR + 4) = b;
        }
        __syncthreads();

        // ---- GEMM: W scalar regs (dup'd per use), z natural-packed broadcast ----
        ull a00=0,a01=0,a02=0,a03=0, a10=0,a11=0,a12=0,a13=0;
        {
            const float* zb = szc + (wid*4)*ZSTR;
            #pragma unroll
            for (int t = 0; t < 8; ++t) {
                const float* zt = zb + t*(64*ZSTR);
                #pragma unroll
                for (int j2 = 0; j2 < 4; ++j2) {
                    const float* q = zt + j2*ZSTR;
                    const ulonglong2 zA = *(const ulonglong2*)(q);
                    const ulonglong2 zB = *(const ulonglong2*)(q + 4);
                    const ull wd0 = pk2(w0[t*4+j2]);
                    const ull wd1 = pk2(w1[t*4+j2]);
                    fma2(a00, wd0, zA.x); fma2(a01, wd0, zA.y);
                    fma2(a02, wd0, zB.x); fma2(a03, wd0, zB.y);
                    fma2(a10, wd1, zA.x); fma2(a11, wd1, zA.y);
                    fma2(a12, wd1, zB.x); fma2(a13, wd1, zB.y);
                }
            }
        }
        // ---- partials: sRed[wid][row][col], row stride 12 ----
        {
            float* rp = sRed + wid*768 + (2*lane)*ZSTR;
            ulonglong2 s0; s0.x = a00; s0.y = a01; *(ulonglong2*)(rp)            = s0;
            ulonglong2 s1; s1.x = a02; s1.y = a03; *(ulonglong2*)(rp + 4)        = s1;
            ulonglong2 s2; s2.x = a10; s2.y = a11; *(ulonglong2*)(rp + ZSTR)     = s2;
            ulonglong2 s3; s3.x = a12; s3.y = a13; *(ulonglong2*)(rp + ZSTR + 4) = s3;
        }
        __syncthreads();

        // ---- combine + relu + publish + local-stage-next (all 512 threads) ----
        {
            float s = 0.f;
            const float* rq = sRed + r*ZSTR + c;
            #pragma unroll
            for (int q = 0; q < 16; ++q) s += rq[q*768];
            const float u  = sUx[tid];
            const float zo = szc[(mi*64 + r)*ZSTR + c];
            const float v  = fmaf(0.5f, zo, 0.5f * (s + u));
            const float zn = fmaxf(v, 0.f);
            __stcg(&gz_nxt[nj*4096 + mi*512 + tid], zn);
            sZ[(cur^1)*6144 + (mi*64 + r)*ZSTR + c] = zn;
        }
        __syncthreads();
        if (tid == 0) bar_arrive(bcnt, bgen);

        { float* t = gz_cur; gz_cur = gz_nxt; gz_nxt = t; }
        cur ^= 1;
    }

    // final: all z40 published
    if (tid == 0) bar_wait(bgen, gen0 + (unsigned)ITERS);
    __syncthreads();

    // ================= Classifier (row-tile 0 CTA of each group) ====================
    if (mi == 0 && tid < 8*CDIM) {
        const int bl = tid / CDIM, cc = tid - bl*CDIM;
        const float* zp = gz_cur + nj*4096 + bl;
        const float* wc = Wc + cc*NDIM;
        float acc = bcv[cc];
        #pragma unroll 8
        for (int n = 0; n < NDIM; ++n)
            acc = fmaf(__ldcg(zp + n*8), wc[n], acc);
        out[(nj*8 + bl)*CDIM + cc] = acc;
    }
}

extern "C" void kernel_launch(void* const* d_in, const int* in_sizes, int n_in,
                              void* d_out, int out_size) {
    (void)in_sizes; (void)n_in; (void)out_size;
    cudaFuncSetAttribute(mondeq_kernel, cudaFuncAttributeMaxDynamicSharedMemorySize, SMEM_BYTES);
    mondeq_kernel<<<GRID, TPB, SMEM_BYTES>>>(
        (const float*)d_in[0],   // W  (512,512)
        (const float*)d_in[1],   // U  (512,784)
        (const float*)d_in[2],   // b  (512)
        (const float*)d_in[3],   // x  (128,784)
        (const float*)d_in[4],   // Wc (10,512)
        (const float*)d_in[5],   // bc (10)
        (float*)d_out);          // logits (128,10)
}